// round 4
// baseline (speedup 1.0000x reference)
#include <cuda_runtime.h>
#include <cuda_bf16.h>
#include <cstdint>

// Problem dims — FIXED by the dataset (reference hardcodes them).
#define N_NODES 100000
#define N_EDGES 1600000
#define IN_C    128
#define HID_C   128
#define OUT_C   40

// ---------------- scratch (static __device__ globals; no allocation) --------
__device__ float g_h1 [(size_t)N_NODES * HID_C];   // 51.2 MB
__device__ float g_agg[(size_t)N_NODES * HID_C];   // 51.2 MB
__device__ float g_t  [(size_t)N_NODES * OUT_C];   // 16 MB
__device__ float g_deg_out[N_NODES];
__device__ float g_deg_in [N_NODES];
__device__ float g_iso[N_NODES];   // out-degree^{-1/2}
__device__ float g_isi[N_NODES];   // in-degree^{-1/2}
__device__ int   g_src[N_EDGES];
__device__ int   g_dst[N_EDGES];
__device__ int   g_mode;           // 0=int32, 1=int64, 2=float32, 3=float64

// ---------------- dtype probe ------------------------------------------------
// Sample first 512 int32 words — safe under every candidate interpretation
// (buffer is at least 2*N_EDGES 4-byte words in all of them).
__global__ void k_detect(const int* __restrict__ w32) {
    if (blockIdx.x != 0 || threadIdx.x != 0) return;
    int oz = 0, ez = 0, ir = 0;
    for (int i = 0; i < 512; i++) {
        int w = w32[i];
        if (w == 0) { if (i & 1) oz++; else ez++; }
        if (w >= 0 && w < N_NODES) ir++;
    }
    int mode;
    if (oz > 240)      mode = 1;   // int64 LE: high words zero
    else if (ez > 240) mode = 3;   // float64 of small ints: low mantissa words zero
    else if (ir > 500) mode = 0;   // int32: every word a valid node id
    else               mode = 2;   // float32 bit patterns
    g_mode = mode;
}

__global__ void k_convert(const void* __restrict__ ei) {
    int i = blockIdx.x * blockDim.x + threadIdx.x;
    if (i >= 2 * N_EDGES) return;
    int mode = g_mode;
    long long v;
    if (mode == 1)      v = ((const long long*)ei)[i];
    else if (mode == 0) v = (long long)((const int*)ei)[i];
    else if (mode == 2) v = (long long)((const float*)ei)[i];
    else                v = (long long)((const double*)ei)[i];
    int vi = (int)v;
    if (vi < 0) vi = 0;
    if (vi >= N_NODES) vi = N_NODES - 1;
    if (i < N_EDGES) g_src[i] = vi;
    else             g_dst[i - N_EDGES] = vi;
}

// ---------------- zero ------------------------------------------------------
__global__ void k_zero(float* __restrict__ out) {
    int tid = blockIdx.x * blockDim.x + threadIdx.x;
    int stride = gridDim.x * blockDim.x;
    const size_t aggN = (size_t)N_NODES * HID_C / 4;
    float4 z = make_float4(0.f, 0.f, 0.f, 0.f);
    float4* agg4 = reinterpret_cast<float4*>(g_agg);
    for (size_t i = tid; i < aggN; i += stride) agg4[i] = z;
    const size_t outN = (size_t)N_NODES * OUT_C / 4;
    float4* out4 = reinterpret_cast<float4*>(out);
    for (size_t i = tid; i < outN; i += stride) out4[i] = z;
    for (int i = tid; i < N_NODES; i += stride) { g_deg_out[i] = 0.f; g_deg_in[i] = 0.f; }
}

// ---------------- degrees ---------------------------------------------------
__global__ void k_deg() {
    int e = blockIdx.x * blockDim.x + threadIdx.x;
    if (e >= N_EDGES) return;
    atomicAdd(&g_deg_out[g_src[e]], 1.f);
    atomicAdd(&g_deg_in [g_dst[e]], 1.f);
}

__global__ void k_isqrt() {
    int i = blockIdx.x * blockDim.x + threadIdx.x;
    if (i >= N_NODES) return;
    g_iso[i] = rsqrtf(fmaxf(g_deg_out[i], 1.f));
    g_isi[i] = rsqrtf(fmaxf(g_deg_in[i], 1.f));
}

// ---------------- GEMM1 (simple): g_h1[node] = (x[node]*iso[node]) @ W1 -----
// One block per node, 128 threads = 128 output cols. x row broadcast via smem,
// W row reads fully coalesced and L2-resident (64 KB).
__global__ __launch_bounds__(128)
void k_gemm1_simple(const float* __restrict__ x, const float* __restrict__ W) {
    __shared__ float xs[IN_C];
    const int node = blockIdx.x;
    const int col = threadIdx.x;
    xs[col] = x[(size_t)node * IN_C + col] * g_iso[node];
    __syncthreads();
    float acc = 0.f;
    #pragma unroll 8
    for (int k = 0; k < IN_C; k++)
        acc += xs[k] * W[(size_t)k * HID_C + col];
    g_h1[(size_t)node * HID_C + col] = acc;
}

// ---------------- scatter 1: g_agg[dst] += g_h1[src]  (plain atomicAdd) -----
__global__ __launch_bounds__(256)
void k_scatter1() {
    int gt = blockIdx.x * blockDim.x + threadIdx.x;   // E*32 items
    int e = gt >> 5;
    int c = gt & 31;                                   // float4 chunk 0..31
    if (e >= N_EDGES) return;
    int s = g_src[e];
    int d = g_dst[e];
    float4 v = *(reinterpret_cast<const float4*>(g_h1 + (size_t)s * HID_C) + c);
    float* p = g_agg + (size_t)d * HID_C + c * 4;
    atomicAdd(p + 0, v.x);
    atomicAdd(p + 1, v.y);
    atomicAdd(p + 2, v.z);
    atomicAdd(p + 3, v.w);
}

// ---------------- GEMM2 (simple): g_t[node] = (relu(agg)*isi*iso) @ W2 ------
// One block per node, 128 threads load+transform the row; threads 0..39 compute.
__global__ __launch_bounds__(128)
void k_gemm2_simple(const float* __restrict__ W2) {
    __shared__ float as[HID_C];
    const int node = blockIdx.x;
    const int t = threadIdx.x;
    float sc = g_iso[node] * g_isi[node];
    as[t] = fmaxf(g_agg[(size_t)node * HID_C + t], 0.f) * sc;
    __syncthreads();
    if (t < OUT_C) {
        float acc = 0.f;
        #pragma unroll 8
        for (int k = 0; k < HID_C; k++)
            acc += as[k] * W2[(size_t)k * OUT_C + t];
        g_t[(size_t)node * OUT_C + t] = acc;
    }
}

// ---------------- scatter 2: out[dst] += g_t[src]  (plain atomicAdd) --------
__global__ __launch_bounds__(256)
void k_scatter2(float* __restrict__ out) {
    int gt = blockIdx.x * blockDim.x + threadIdx.x;   // E*10 items
    int e = gt / 10;
    int c = gt - e * 10;                               // float4 chunk 0..9
    if (e >= N_EDGES) return;
    int s = g_src[e];
    int d = g_dst[e];
    float4 v = *reinterpret_cast<const float4*>(g_t + (size_t)s * OUT_C + c * 4);
    float* p = out + (size_t)d * OUT_C + c * 4;
    atomicAdd(p + 0, v.x);
    atomicAdd(p + 1, v.y);
    atomicAdd(p + 2, v.z);
    atomicAdd(p + 3, v.w);
}

// ---------------- final scale: out *= isi[node] -----------------------------
__global__ void k_final_scale(float* __restrict__ out) {
    int i = blockIdx.x * blockDim.x + threadIdx.x;
    const int total = N_NODES * (OUT_C / 4);
    if (i >= total) return;
    int node = i / (OUT_C / 4);
    float s = g_isi[node];
    float4* p = reinterpret_cast<float4*>(out) + i;
    float4 v = *p;
    v.x *= s; v.y *= s; v.z *= s; v.w *= s;
    *p = v;
}

// ---------------- launch ----------------------------------------------------
extern "C" void kernel_launch(void* const* d_in, const int* in_sizes, int n_in,
                              void* d_out, int out_size) {
    const float* x  = (const float*)d_in[0];
    const void*  ei = d_in[1];
    const float* W1 = (const float*)d_in[2];
    const float* W2 = (const float*)d_in[3];
    float* out = (float*)d_out;

    // 0) probe dtype of edge_index, convert to packed int32 src/dst
    k_detect<<<1, 32>>>((const int*)ei);
    k_convert<<<(2 * N_EDGES + 255) / 256, 256>>>(ei);

    // 1) zero scratch + out + degree arrays
    k_zero<<<1024, 256>>>(out);

    // 2) degrees -> 3) isqrt
    k_deg<<<(N_EDGES + 255) / 256, 256>>>();
    k_isqrt<<<(N_NODES + 255) / 256, 256>>>();

    // 4) layer-1 projection
    k_gemm1_simple<<<N_NODES, 128>>>(x, W1);

    // 5) layer-1 aggregation
    {
        long long items = (long long)N_EDGES * 32;
        int blocks = (int)((items + 255) / 256);
        k_scatter1<<<blocks, 256>>>();
    }

    // 6) layer-2 projection (relu + both norms fused)
    k_gemm2_simple<<<N_NODES, 128>>>(W2);

    // 7) layer-2 aggregation into d_out
    {
        long long items = (long long)N_EDGES * 10;
        int blocks = (int)((items + 255) / 256);
        k_scatter2<<<blocks, 256>>>(out);
    }

    // 8) final in-degree normalization
    k_final_scale<<<(N_NODES * (OUT_C / 4) + 255) / 256, 256>>>(out);
}

// round 6
// speedup vs baseline: 1.4308x; 1.4308x over previous
#include <cuda_runtime.h>
#include <cuda_bf16.h>
#include <cstdint>

// Problem dims — FIXED by the dataset (reference hardcodes them).
#define N_NODES 100000
#define N_EDGES 1600000
#define IN_C    128
#define HID_C   128
#define OUT_C   40

#define SCAN_T  1024

// ---------------- scratch (static __device__ globals; no allocation) --------
__device__ float g_h1 [(size_t)N_NODES * HID_C];   // 51.2 MB
__device__ float g_agg[(size_t)N_NODES * HID_C];   // 51.2 MB
__device__ float g_t  [(size_t)N_NODES * OUT_C];   // 16 MB
__device__ int   g_degi[N_NODES];                  // in-degree
__device__ int   g_dego[N_NODES];                  // out-degree
__device__ float g_iso[N_NODES];                   // out-degree^{-1/2}
__device__ float g_isi[N_NODES];                   // in-degree^{-1/2}
__device__ int   g_src[N_EDGES];
__device__ int   g_dst[N_EDGES];
__device__ int   g_row[N_NODES + 1];               // CSR row offsets (by dst)
__device__ int   g_cur[N_NODES];                   // fill cursors
__device__ int   g_eidx[N_EDGES];                  // CSR: src ids grouped by dst
__device__ int   g_mode;                           // edge dtype

// ---------------- dtype probe ------------------------------------------------
__global__ void k_detect(const int* __restrict__ w32) {
    if (blockIdx.x != 0 || threadIdx.x != 0) return;
    int oz = 0, ez = 0, ir = 0;
    for (int i = 0; i < 512; i++) {
        int w = w32[i];
        if (w == 0) { if (i & 1) oz++; else ez++; }
        if (w >= 0 && w < N_NODES) ir++;
    }
    int mode;
    if (oz > 240)      mode = 1;   // int64
    else if (ez > 240) mode = 3;   // float64
    else if (ir > 500) mode = 0;   // int32
    else               mode = 2;   // float32
    g_mode = mode;
}

__global__ void k_convert(const void* __restrict__ ei) {
    int i = blockIdx.x * blockDim.x + threadIdx.x;
    if (i >= 2 * N_EDGES) return;
    int mode = g_mode;
    long long v;
    if (mode == 1)      v = ((const long long*)ei)[i];
    else if (mode == 0) v = (long long)((const int*)ei)[i];
    else if (mode == 2) v = (long long)((const float*)ei)[i];
    else                v = (long long)((const double*)ei)[i];
    int vi = (int)v;
    if (vi < 0) vi = 0;
    if (vi >= N_NODES) vi = N_NODES - 1;
    if (i < N_EDGES) g_src[i] = vi;
    else             g_dst[i - N_EDGES] = vi;
}

// ---------------- degrees + normalization -----------------------------------
__global__ void k_zero_deg() {
    int i = blockIdx.x * blockDim.x + threadIdx.x;
    if (i < N_NODES) { g_degi[i] = 0; g_dego[i] = 0; }
}

__global__ void k_deg() {
    int e = blockIdx.x * blockDim.x + threadIdx.x;
    if (e >= N_EDGES) return;
    atomicAdd(&g_dego[g_src[e]], 1);
    atomicAdd(&g_degi[g_dst[e]], 1);
}

__global__ void k_isqrt() {
    int i = blockIdx.x * blockDim.x + threadIdx.x;
    if (i >= N_NODES) return;
    g_iso[i] = rsqrtf((float)max(g_dego[i], 1));
    g_isi[i] = rsqrtf((float)max(g_degi[i], 1));
}

// ---------------- CSR build --------------------------------------------------
__global__ __launch_bounds__(SCAN_T)
void k_scan() {
    __shared__ int part[SCAN_T];
    const int t = threadIdx.x;
    const int per = (N_NODES + SCAN_T - 1) / SCAN_T;
    int start = t * per;
    int end = min(start + per, N_NODES);
    int s = 0;
    for (int i = start; i < end; i++) s += g_degi[i];
    part[t] = s;
    __syncthreads();
    for (int off = 1; off < SCAN_T; off <<= 1) {
        int v = (t >= off) ? part[t - off] : 0;
        __syncthreads();
        part[t] += v;
        __syncthreads();
    }
    int run = (t == 0) ? 0 : part[t - 1];
    for (int i = start; i < end; i++) {
        g_row[i] = run;
        g_cur[i] = run;
        run += g_degi[i];
    }
    if (t == SCAN_T - 1) g_row[N_NODES] = run;
}

__global__ void k_fill() {
    int e = blockIdx.x * blockDim.x + threadIdx.x;
    if (e >= N_EDGES) return;
    int d = g_dst[e];
    int pos = atomicAdd(&g_cur[d], 1);
    g_eidx[pos] = g_src[e];
}

// ---------------- GEMM1 (simple, PROVEN): h1 = (x*iso) @ W1 -----------------
__global__ __launch_bounds__(128)
void k_gemm1_simple(const float* __restrict__ x, const float* __restrict__ W) {
    __shared__ float xs[IN_C];
    const int node = blockIdx.x;
    const int col = threadIdx.x;
    xs[col] = x[(size_t)node * IN_C + col] * g_iso[node];
    __syncthreads();
    float acc = 0.f;
    #pragma unroll 8
    for (int k = 0; k < IN_C; k++)
        acc += xs[k] * W[(size_t)k * HID_C + col];
    g_h1[(size_t)node * HID_C + col] = acc;
}

// ---------------- gather 1: g_agg[d] = sum_{s in CSR[d]} g_h1[s] ------------
// One warp per destination node; lane owns one float4 chunk of the 128-f row.
__global__ __launch_bounds__(256)
void k_agg1() {
    int w = (blockIdx.x * blockDim.x + threadIdx.x) >> 5;
    int lane = threadIdx.x & 31;
    if (w >= N_NODES) return;
    int beg = g_row[w], end = g_row[w + 1];
    float4 acc = make_float4(0.f, 0.f, 0.f, 0.f);
    for (int j = beg; j < end; j++) {
        int s = g_eidx[j];   // uniform across warp -> broadcast
        float4 v = *(reinterpret_cast<const float4*>(g_h1 + (size_t)s * HID_C) + lane);
        acc.x += v.x; acc.y += v.y; acc.z += v.z; acc.w += v.w;
    }
    *(reinterpret_cast<float4*>(g_agg + (size_t)w * HID_C) + lane) = acc;
}

// ---------------- GEMM2 (simple, PROVEN): t = (relu(agg)*isi*iso) @ W2 ------
__global__ __launch_bounds__(128)
void k_gemm2_simple(const float* __restrict__ W2) {
    __shared__ float as[HID_C];
    const int node = blockIdx.x;
    const int t = threadIdx.x;
    float sc = g_iso[node] * g_isi[node];
    as[t] = fmaxf(g_agg[(size_t)node * HID_C + t], 0.f) * sc;
    __syncthreads();
    if (t < OUT_C) {
        float acc = 0.f;
        #pragma unroll 8
        for (int k = 0; k < HID_C; k++)
            acc += as[k] * W2[(size_t)k * OUT_C + t];
        g_t[(size_t)node * OUT_C + t] = acc;
    }
}

// ---------------- gather 2: out[d] = isi[d] * sum g_t[s] --------------------
// One warp per node; lanes 0..9 own one float4 chunk each (40 floats).
__global__ __launch_bounds__(256)
void k_agg2(float* __restrict__ out) {
    int w = (blockIdx.x * blockDim.x + threadIdx.x) >> 5;
    int lane = threadIdx.x & 31;
    if (w >= N_NODES || lane >= 10) return;
    int beg = g_row[w], end = g_row[w + 1];
    float4 acc = make_float4(0.f, 0.f, 0.f, 0.f);
    for (int j = beg; j < end; j++) {
        int s = g_eidx[j];
        float4 v = *reinterpret_cast<const float4*>(g_t + (size_t)s * OUT_C + lane * 4);
        acc.x += v.x; acc.y += v.y; acc.z += v.z; acc.w += v.w;
    }
    float sc = g_isi[w];
    acc.x *= sc; acc.y *= sc; acc.z *= sc; acc.w *= sc;
    *reinterpret_cast<float4*>(out + (size_t)w * OUT_C + lane * 4) = acc;
}

// ---------------- launch ----------------------------------------------------
extern "C" void kernel_launch(void* const* d_in, const int* in_sizes, int n_in,
                              void* d_out, int out_size) {
    const float* x  = (const float*)d_in[0];
    const void*  ei = d_in[1];
    const float* W1 = (const float*)d_in[2];
    const float* W2 = (const float*)d_in[3];
    float* out = (float*)d_out;

    // 0) edge dtype probe + int32 conversion
    k_detect<<<1, 32>>>((const int*)ei);
    k_convert<<<(2 * N_EDGES + 255) / 256, 256>>>(ei);

    // 1) degrees + norms
    k_zero_deg<<<(N_NODES + 255) / 256, 256>>>();
    k_deg<<<(N_EDGES + 255) / 256, 256>>>();
    k_isqrt<<<(N_NODES + 255) / 256, 256>>>();

    // 2) CSR by destination
    k_scan<<<1, SCAN_T>>>();
    k_fill<<<(N_EDGES + 255) / 256, 256>>>();

    // 3) layer-1 projection (simple GEMM — proven in round 4)
    k_gemm1_simple<<<N_NODES, 128>>>(x, W1);

    // 4) layer-1 aggregation (CSR gather, no atomics)
    k_agg1<<<(N_NODES * 32 + 255) / 256, 256>>>();

    // 5) layer-2 projection (simple GEMM — proven in round 4)
    k_gemm2_simple<<<N_NODES, 128>>>(W2);

    // 6) layer-2 aggregation + final scale, straight into d_out
    k_agg2<<<(N_NODES * 32 + 255) / 256, 256>>>(out);
}

// round 7
// speedup vs baseline: 1.9781x; 1.3825x over previous
#include <cuda_runtime.h>
#include <cuda_bf16.h>
#include <cstdint>

// Problem dims — FIXED by the dataset (reference hardcodes them).
#define N_NODES 100000
#define N_EDGES 1600000
#define IN_C    128
#define HID_C   128
#define OUT_C   40

#define SCAN_T  1024
#define NPB1    8     // nodes per block, GEMM1 (100000 % 8 == 0)
#define NPB2    16    // nodes per block, GEMM2 (100000 % 16 == 0)

// ---------------- scratch (static __device__ globals; no allocation) --------
__device__ float g_h1 [(size_t)N_NODES * HID_C];   // 51.2 MB
__device__ float g_agg[(size_t)N_NODES * HID_C];   // 51.2 MB
__device__ float g_t  [(size_t)N_NODES * OUT_C];   // 16 MB
__device__ int   g_degi[N_NODES];                  // in-degree
__device__ int   g_dego[N_NODES];                  // out-degree
__device__ float g_iso[N_NODES];                   // out-degree^{-1/2}
__device__ float g_isi[N_NODES];                   // in-degree^{-1/2}
__device__ int   g_src[N_EDGES];
__device__ int   g_dst[N_EDGES];
__device__ int   g_row[N_NODES + 1];               // CSR row offsets (by dst)
__device__ int   g_cur[N_NODES];                   // fill cursors
__device__ int   g_eidx[N_EDGES];                  // CSR: src ids grouped by dst
__device__ int   g_mode;                           // edge dtype

// ---------------- dtype probe ------------------------------------------------
__global__ void k_detect(const int* __restrict__ w32) {
    if (blockIdx.x != 0 || threadIdx.x != 0) return;
    int oz = 0, ez = 0, ir = 0;
    for (int i = 0; i < 512; i++) {
        int w = w32[i];
        if (w == 0) { if (i & 1) oz++; else ez++; }
        if (w >= 0 && w < N_NODES) ir++;
    }
    int mode;
    if (oz > 240)      mode = 1;   // int64
    else if (ez > 240) mode = 3;   // float64
    else if (ir > 500) mode = 0;   // int32
    else               mode = 2;   // float32
    g_mode = mode;
}

// ---------------- convert + degree histogram (fused) -------------------------
__global__ void k_zero_deg() {
    int i = blockIdx.x * blockDim.x + threadIdx.x;
    if (i < N_NODES) { g_degi[i] = 0; g_dego[i] = 0; }
}

__global__ void k_convert(const void* __restrict__ ei) {
    int i = blockIdx.x * blockDim.x + threadIdx.x;
    if (i >= 2 * N_EDGES) return;
    int mode = g_mode;
    long long v;
    if (mode == 1)      v = ((const long long*)ei)[i];
    else if (mode == 0) v = (long long)((const int*)ei)[i];
    else if (mode == 2) v = (long long)((const float*)ei)[i];
    else                v = (long long)((const double*)ei)[i];
    int vi = (int)v;
    if (vi < 0) vi = 0;
    if (vi >= N_NODES) vi = N_NODES - 1;
    if (i < N_EDGES) { g_src[i] = vi;           atomicAdd(&g_dego[vi], 1); }
    else             { g_dst[i - N_EDGES] = vi; atomicAdd(&g_degi[vi], 1); }
}

__global__ void k_isqrt() {
    int i = blockIdx.x * blockDim.x + threadIdx.x;
    if (i >= N_NODES) return;
    g_iso[i] = rsqrtf((float)max(g_dego[i], 1));
    g_isi[i] = rsqrtf((float)max(g_degi[i], 1));
}

// ---------------- CSR build --------------------------------------------------
__global__ __launch_bounds__(SCAN_T)
void k_scan() {
    __shared__ int part[SCAN_T];
    const int t = threadIdx.x;
    const int per = (N_NODES + SCAN_T - 1) / SCAN_T;
    int start = t * per;
    int end = min(start + per, N_NODES);
    int s = 0;
    for (int i = start; i < end; i++) s += g_degi[i];
    part[t] = s;
    __syncthreads();
    for (int off = 1; off < SCAN_T; off <<= 1) {
        int v = (t >= off) ? part[t - off] : 0;
        __syncthreads();
        part[t] += v;
        __syncthreads();
    }
    int run = (t == 0) ? 0 : part[t - 1];
    for (int i = start; i < end; i++) {
        g_row[i] = run;
        g_cur[i] = run;
        run += g_degi[i];
    }
    if (t == SCAN_T - 1) g_row[N_NODES] = run;
}

__global__ void k_fill() {
    int e = blockIdx.x * blockDim.x + threadIdx.x;
    if (e >= N_EDGES) return;
    int d = g_dst[e];
    int pos = atomicAdd(&g_cur[d], 1);
    g_eidx[pos] = g_src[e];
}

// ---------------- GEMM1: h1 = (x*iso) @ W1, 8 nodes/block -------------------
// Thread t = output column. Per k: 1 LDG of W (L1-resident) + 2 LDS.128 + 8 FMA.
__global__ __launch_bounds__(128)
void k_gemm1_multi(const float* __restrict__ x, const float* __restrict__ W) {
    __shared__ __align__(16) float xs[IN_C][NPB1];   // [k][n]
    const int node0 = blockIdx.x * NPB1;
    const int t = threadIdx.x;
    #pragma unroll
    for (int n = 0; n < NPB1; n++)
        xs[t][n] = x[(size_t)(node0 + n) * IN_C + t] * g_iso[node0 + n];
    __syncthreads();

    float acc[NPB1];
    #pragma unroll
    for (int n = 0; n < NPB1; n++) acc[n] = 0.f;

    #pragma unroll 4
    for (int k = 0; k < IN_C; k++) {
        float w = W[(size_t)k * HID_C + t];
        float4 a = *reinterpret_cast<const float4*>(&xs[k][0]);
        float4 b = *reinterpret_cast<const float4*>(&xs[k][4]);
        acc[0] += a.x * w; acc[1] += a.y * w; acc[2] += a.z * w; acc[3] += a.w * w;
        acc[4] += b.x * w; acc[5] += b.y * w; acc[6] += b.z * w; acc[7] += b.w * w;
    }
    #pragma unroll
    for (int n = 0; n < NPB1; n++)
        g_h1[(size_t)(node0 + n) * HID_C + t] = acc[n];
}

// ---------------- gather 1: g_agg[d] = sum_{s in CSR[d]} g_h1[s] ------------
__global__ __launch_bounds__(256)
void k_agg1() {
    int w = (blockIdx.x * blockDim.x + threadIdx.x) >> 5;
    int lane = threadIdx.x & 31;
    if (w >= N_NODES) return;
    int beg = g_row[w], end = g_row[w + 1];
    float4 acc = make_float4(0.f, 0.f, 0.f, 0.f);
    for (int j = beg; j < end; j++) {
        int s = g_eidx[j];   // uniform across warp -> broadcast
        float4 v = *(reinterpret_cast<const float4*>(g_h1 + (size_t)s * HID_C) + lane);
        acc.x += v.x; acc.y += v.y; acc.z += v.z; acc.w += v.w;
    }
    *(reinterpret_cast<float4*>(g_agg + (size_t)w * HID_C) + lane) = acc;
}

// ---------------- GEMM2: t = (relu(agg)*isi*iso) @ W2, 16 nodes/block -------
// Thread = (col in 0..63 [40 valid], node-group of 4). Per k: 1 LDG + 4 LDS + 4 FMA.
__global__ __launch_bounds__(256)
void k_gemm2_multi(const float* __restrict__ W2) {
    __shared__ float as[HID_C][NPB2 + 1];   // pad -> conflict-free staging stores
    __shared__ float scs[NPB2];
    const int node0 = blockIdx.x * NPB2;
    const int t = threadIdx.x;
    if (t < NPB2) scs[t] = g_iso[node0 + t] * g_isi[node0 + t];
    __syncthreads();

    #pragma unroll
    for (int i = 0; i < (HID_C * NPB2) / 256; i++) {   // 8 staging items/thread
        int item = i * 256 + t;
        int n = item >> 7;          // item / HID_C
        int k = item & (HID_C - 1);
        as[k][n] = fmaxf(g_agg[(size_t)(node0 + n) * HID_C + k], 0.f) * scs[n];
    }
    __syncthreads();

    const int col = t & 63;
    const int grp = t >> 6;         // nodes grp*4 .. grp*4+3
    if (col < OUT_C) {
        float acc0 = 0.f, acc1 = 0.f, acc2 = 0.f, acc3 = 0.f;
        #pragma unroll 4
        for (int k = 0; k < HID_C; k++) {
            float wv = W2[(size_t)k * OUT_C + col];
            acc0 += as[k][grp * 4 + 0] * wv;
            acc1 += as[k][grp * 4 + 1] * wv;
            acc2 += as[k][grp * 4 + 2] * wv;
            acc3 += as[k][grp * 4 + 3] * wv;
        }
        g_t[(size_t)(node0 + grp * 4 + 0) * OUT_C + col] = acc0;
        g_t[(size_t)(node0 + grp * 4 + 1) * OUT_C + col] = acc1;
        g_t[(size_t)(node0 + grp * 4 + 2) * OUT_C + col] = acc2;
        g_t[(size_t)(node0 + grp * 4 + 3) * OUT_C + col] = acc3;
    }
}

// ---------------- gather 2: out[d] = isi[d] * sum g_t[s] --------------------
__global__ __launch_bounds__(256)
void k_agg2(float* __restrict__ out) {
    int w = (blockIdx.x * blockDim.x + threadIdx.x) >> 5;
    int lane = threadIdx.x & 31;
    if (w >= N_NODES || lane >= 10) return;
    int beg = g_row[w], end = g_row[w + 1];
    float4 acc = make_float4(0.f, 0.f, 0.f, 0.f);
    for (int j = beg; j < end; j++) {
        int s = g_eidx[j];
        float4 v = *reinterpret_cast<const float4*>(g_t + (size_t)s * OUT_C + lane * 4);
        acc.x += v.x; acc.y += v.y; acc.z += v.z; acc.w += v.w;
    }
    float sc = g_isi[w];
    acc.x *= sc; acc.y *= sc; acc.z *= sc; acc.w *= sc;
    *reinterpret_cast<float4*>(out + (size_t)w * OUT_C + lane * 4) = acc;
}

// ---------------- launch ----------------------------------------------------
extern "C" void kernel_launch(void* const* d_in, const int* in_sizes, int n_in,
                              void* d_out, int out_size) {
    const float* x  = (const float*)d_in[0];
    const void*  ei = d_in[1];
    const float* W1 = (const float*)d_in[2];
    const float* W2 = (const float*)d_in[3];
    float* out = (float*)d_out;

    // 0) edge dtype probe; zero degrees; convert + degree histogram (fused)
    k_detect<<<1, 32>>>((const int*)ei);
    k_zero_deg<<<(N_NODES + 255) / 256, 256>>>();
    k_convert<<<(2 * N_EDGES + 255) / 256, 256>>>(ei);
    k_isqrt<<<(N_NODES + 255) / 256, 256>>>();

    // 1) CSR by destination
    k_scan<<<1, SCAN_T>>>();
    k_fill<<<(N_EDGES + 255) / 256, 256>>>();

    // 2) layer-1 projection (multi-node, W-load amortized)
    k_gemm1_multi<<<N_NODES / NPB1, 128>>>(x, W1);

    // 3) layer-1 aggregation (CSR gather, no atomics)
    k_agg1<<<(N_NODES * 32 + 255) / 256, 256>>>();

    // 4) layer-2 projection (relu + both norms fused)
    k_gemm2_multi<<<N_NODES / NPB2, 256>>>(W2);

    // 5) layer-2 aggregation + final scale, straight into d_out
    k_agg2<<<(N_NODES * 32 + 255) / 256, 256>>>(out);
}

// round 8
// speedup vs baseline: 2.6831x; 1.3564x over previous
#include <cuda_runtime.h>
#include <cuda_bf16.h>
#include <cstdint>

// Problem dims — FIXED by the dataset (reference hardcodes them).
#define N_NODES 100000
#define N_EDGES 1600000
#define IN_C    128
#define HID_C   128
#define OUT_C   40

#define NPB1    8     // nodes per block, GEMM1 (100000 % 8 == 0)
#define WPB     8     // warps per block in fused agg kernel

// ---------------- scratch (static __device__ globals; no allocation) --------
__device__ float g_h1 [(size_t)N_NODES * HID_C];   // 51.2 MB
__device__ float g_t  [(size_t)N_NODES * OUT_C];   // 16 MB
__device__ int   g_degi[N_NODES];                  // in-degree
__device__ int   g_dego[N_NODES];                  // out-degree
__device__ float g_iso[N_NODES];                   // out-degree^{-1/2}
__device__ float g_isi[N_NODES];                   // in-degree^{-1/2}
__device__ int   g_src[N_EDGES];
__device__ int   g_dst[N_EDGES];
__device__ int   g_row[N_NODES];                   // CSR segment start (by dst)
__device__ int   g_cur[N_NODES];                   // fill cursors
__device__ int   g_eidx[N_EDGES];                  // CSR: src ids grouped by dst
__device__ int   g_mode;                           // edge dtype
__device__ int   g_total;                          // CSR allocation counter

// ---------------- dtype probe ------------------------------------------------
__global__ void k_detect(const int* __restrict__ w32) {
    if (blockIdx.x != 0 || threadIdx.x != 0) return;
    int oz = 0, ez = 0, ir = 0;
    for (int i = 0; i < 512; i++) {
        int w = w32[i];
        if (w == 0) { if (i & 1) oz++; else ez++; }
        if (w >= 0 && w < N_NODES) ir++;
    }
    int mode;
    if (oz > 240)      mode = 1;   // int64
    else if (ez > 240) mode = 3;   // float64
    else if (ir > 500) mode = 0;   // int32
    else               mode = 2;   // float32
    g_mode = mode;
}

// ---------------- zero + convert + degree histogram --------------------------
__global__ void k_zero_deg() {
    int i = blockIdx.x * blockDim.x + threadIdx.x;
    if (i < N_NODES) { g_degi[i] = 0; g_dego[i] = 0; }
    if (i == 0) g_total = 0;
}

__global__ void k_convert(const void* __restrict__ ei) {
    int i = blockIdx.x * blockDim.x + threadIdx.x;
    if (i >= 2 * N_EDGES) return;
    int mode = g_mode;
    long long v;
    if (mode == 1)      v = ((const long long*)ei)[i];
    else if (mode == 0) v = (long long)((const int*)ei)[i];
    else if (mode == 2) v = (long long)((const float*)ei)[i];
    else                v = (long long)((const double*)ei)[i];
    int vi = (int)v;
    if (vi < 0) vi = 0;
    if (vi >= N_NODES) vi = N_NODES - 1;
    if (i < N_EDGES) { g_src[i] = vi;           atomicAdd(&g_dego[vi], 1); }
    else             { g_dst[i - N_EDGES] = vi; atomicAdd(&g_degi[vi], 1); }
}

// ---------------- norms + CSR segment allocation (fused) ---------------------
__global__ void k_isqrt_alloc() {
    int i = blockIdx.x * blockDim.x + threadIdx.x;
    if (i >= N_NODES) return;
    g_iso[i] = rsqrtf((float)max(g_dego[i], 1));
    g_isi[i] = rsqrtf((float)max(g_degi[i], 1));
    int pos = atomicAdd(&g_total, g_degi[i]);
    g_row[i] = pos;
    g_cur[i] = pos;
}

__global__ void k_fill() {
    int e = blockIdx.x * blockDim.x + threadIdx.x;
    if (e >= N_EDGES) return;
    int d = g_dst[e];
    int pos = atomicAdd(&g_cur[d], 1);
    g_eidx[pos] = g_src[e];
}

// ---------------- GEMM1: h1 = (x*iso) @ W1, 8 nodes/block -------------------
__global__ __launch_bounds__(128)
void k_gemm1_multi(const float* __restrict__ x, const float* __restrict__ W) {
    __shared__ __align__(16) float xs[IN_C][NPB1];   // [k][n]
    const int node0 = blockIdx.x * NPB1;
    const int t = threadIdx.x;
    #pragma unroll
    for (int n = 0; n < NPB1; n++)
        xs[t][n] = x[(size_t)(node0 + n) * IN_C + t] * g_iso[node0 + n];
    __syncthreads();

    float acc[NPB1];
    #pragma unroll
    for (int n = 0; n < NPB1; n++) acc[n] = 0.f;

    #pragma unroll 4
    for (int k = 0; k < IN_C; k++) {
        float w = W[(size_t)k * HID_C + t];
        float4 a = *reinterpret_cast<const float4*>(&xs[k][0]);
        float4 b = *reinterpret_cast<const float4*>(&xs[k][4]);
        acc[0] += a.x * w; acc[1] += a.y * w; acc[2] += a.z * w; acc[3] += a.w * w;
        acc[4] += b.x * w; acc[5] += b.y * w; acc[6] += b.z * w; acc[7] += b.w * w;
    }
    #pragma unroll
    for (int n = 0; n < NPB1; n++)
        g_h1[(size_t)(node0 + n) * HID_C + t] = acc[n];
}

// ---------------- FUSED: agg1 + relu/norm + GEMM2 ----------------------------
// One warp per dst node. Gather-sum h1 rows into registers, relu+scale, stage
// the 128-f row in per-warp smem, multiply by smem-cached W2 -> 40-f g_t row.
__global__ __launch_bounds__(WPB * 32)
void k_agg1_gemm2(const float* __restrict__ W2) {
    __shared__ float W2s[HID_C][OUT_C];            // 20 KB, loaded once
    __shared__ __align__(16) float as[WPB][HID_C]; // per-warp staged row

    const int t = threadIdx.x;
    // Load W2 (5120 floats / 256 threads = 20 each)
    #pragma unroll
    for (int i = 0; i < (HID_C * OUT_C) / (WPB * 32); i++) {
        int item = i * (WPB * 32) + t;
        ((float*)W2s)[item] = W2[item];
    }
    __syncthreads();

    const int wid = t >> 5;
    const int lane = t & 31;
    const int d = blockIdx.x * WPB + wid;
    if (d >= N_NODES) return;

    const int beg = g_row[d];
    const int end = beg + g_degi[d];
    float4 acc = make_float4(0.f, 0.f, 0.f, 0.f);
    for (int j = beg; j < end; j++) {
        int s = g_eidx[j];   // uniform across warp -> broadcast
        float4 v = *(reinterpret_cast<const float4*>(g_h1 + (size_t)s * HID_C) + lane);
        acc.x += v.x; acc.y += v.y; acc.z += v.z; acc.w += v.w;
    }
    // relu + both norms, stage to smem
    const float sc = g_iso[d] * g_isi[d];
    acc.x = fmaxf(acc.x, 0.f) * sc;
    acc.y = fmaxf(acc.y, 0.f) * sc;
    acc.z = fmaxf(acc.z, 0.f) * sc;
    acc.w = fmaxf(acc.w, 0.f) * sc;
    *reinterpret_cast<float4*>(&as[wid][lane * 4]) = acc;
    __syncwarp();

    // GEMM2 for this node: col0 = lane (0..31), col1 = 32+lane (lane<8)
    float acc0 = 0.f, acc1 = 0.f;
    #pragma unroll 8
    for (int k = 0; k < HID_C; k++) {
        float a = as[wid][k];                      // broadcast
        acc0 += a * W2s[k][lane];                  // conflict-free
        if (lane < 8) acc1 += a * W2s[k][32 + lane];
    }
    g_t[(size_t)d * OUT_C + lane] = acc0;
    if (lane < 8) g_t[(size_t)d * OUT_C + 32 + lane] = acc1;
}

// ---------------- gather 2: out[d] = isi[d] * sum g_t[s] --------------------
__global__ __launch_bounds__(256)
void k_agg2(float* __restrict__ out) {
    int w = (blockIdx.x * blockDim.x + threadIdx.x) >> 5;
    int lane = threadIdx.x & 31;
    if (w >= N_NODES || lane >= 10) return;
    int beg = g_row[w];
    int end = beg + g_degi[w];
    float4 acc = make_float4(0.f, 0.f, 0.f, 0.f);
    for (int j = beg; j < end; j++) {
        int s = g_eidx[j];
        float4 v = *reinterpret_cast<const float4*>(g_t + (size_t)s * OUT_C + lane * 4);
        acc.x += v.x; acc.y += v.y; acc.z += v.z; acc.w += v.w;
    }
    float sc = g_isi[w];
    acc.x *= sc; acc.y *= sc; acc.z *= sc; acc.w *= sc;
    *reinterpret_cast<float4*>(out + (size_t)w * OUT_C + lane * 4) = acc;
}

// ---------------- launch ----------------------------------------------------
extern "C" void kernel_launch(void* const* d_in, const int* in_sizes, int n_in,
                              void* d_out, int out_size) {
    const float* x  = (const float*)d_in[0];
    const void*  ei = d_in[1];
    const float* W1 = (const float*)d_in[2];
    const float* W2 = (const float*)d_in[3];
    float* out = (float*)d_out;

    // 0) dtype probe; zero degrees; convert + degree histogram (fused)
    k_detect<<<1, 32>>>((const int*)ei);
    k_zero_deg<<<(N_NODES + 255) / 256, 256>>>();
    k_convert<<<(2 * N_EDGES + 255) / 256, 256>>>(ei);

    // 1) norms + CSR segment allocation (no scan), then fill
    k_isqrt_alloc<<<(N_NODES + 255) / 256, 256>>>();
    k_fill<<<(N_EDGES + 255) / 256, 256>>>();

    // 2) layer-1 projection
    k_gemm1_multi<<<N_NODES / NPB1, 128>>>(x, W1);

    // 3) FUSED layer-1 aggregation + relu/norm + layer-2 projection
    k_agg1_gemm2<<<(N_NODES + WPB - 1) / WPB, WPB * 32>>>(W2);

    // 4) layer-2 aggregation + final scale, straight into d_out
    k_agg2<<<(N_NODES * 32 + 255) / 256, 256>>>(out);
}